// round 2
// baseline (speedup 1.0000x reference)
#include <cuda_runtime.h>
#include <math.h>

#define N_TOK 768
#define D_MODEL 512
#define CZ 128
#define NH 16
#define DH 32
#define LN_EPS 1e-5f

// ---------------- scratch ----------------
__device__ float g_q[N_TOK * D_MODEL];
__device__ float g_k[N_TOK * D_MODEL];
__device__ float g_v[N_TOK * D_MODEL];
__device__ float g_g[N_TOK * D_MODEL];
__device__ float g_o[N_TOK * D_MODEL];
__device__ float g_bias[(size_t)NH * N_TOK * N_TOK];
__device__ float g_A[NH * CZ];
__device__ float g_SA[NH];
__device__ float g_CB[NH];

// ---------------- K0: fold LN affine into Wz ----------------
__global__ void prep_kernel(const float* __restrict__ Wz,
                            const float* __restrict__ lnw,
                            const float* __restrict__ lnb) {
    __shared__ float red[8];
    int c = threadIdx.x;  // 128 threads
    float wc = lnw[c], bc = lnb[c];
    for (int h = 0; h < NH; h++) {
        float wz = Wz[h * CZ + c];
        float a = wz * wc;
        g_A[h * CZ + c] = a;
        float sa = a, cb = wz * bc;
        for (int o = 16; o; o >>= 1) {
            sa += __shfl_down_sync(0xffffffffu, sa, o);
            cb += __shfl_down_sync(0xffffffffu, cb, o);
        }
        if ((c & 31) == 0) { red[c >> 5] = sa; red[4 + (c >> 5)] = cb; }
        __syncthreads();
        if (c == 0) {
            g_SA[h] = red[0] + red[1] + red[2] + red[3];
            g_CB[h] = red[4] + red[5] + red[6] + red[7];
        }
        __syncthreads();
    }
}

// ---------------- K1: q,k,v,g projections: C = s @ W^T (+bias for q) ----------------
// BM=64, BN=128, BK=16, 256 threads, 4x8 per thread
__global__ void proj_kernel(const float* __restrict__ s,
                            const float* __restrict__ Wq, const float* __restrict__ bq,
                            const float* __restrict__ Wk, const float* __restrict__ Wv,
                            const float* __restrict__ Wg) {
    __shared__ float As[16][68];    // As[k][m]
    __shared__ float Bs[16][136];   // Bs[k][n]
    int w = blockIdx.z;
    const float* W = (w == 0) ? Wq : (w == 1) ? Wk : (w == 2) ? Wv : Wg;
    float* C = (w == 0) ? g_q : (w == 1) ? g_k : (w == 2) ? g_v : g_g;
    int bm = blockIdx.y * 64, bn = blockIdx.x * 128;
    int tid = threadIdx.x;
    int tx = tid & 15, ty = tid >> 4;
    float acc[4][8] = {};
    int lrA = tid >> 2, lcA = (tid & 3) * 4;   // 64 rows x 16 cols
    int lrB = tid >> 1, lcB = (tid & 1) * 8;   // 128 rows x 16 cols

    for (int k0 = 0; k0 < D_MODEL; k0 += 16) {
        float4 va = *reinterpret_cast<const float4*>(&s[(bm + lrA) * D_MODEL + k0 + lcA]);
        As[lcA + 0][lrA] = va.x; As[lcA + 1][lrA] = va.y;
        As[lcA + 2][lrA] = va.z; As[lcA + 3][lrA] = va.w;
        float4 vb0 = *reinterpret_cast<const float4*>(&W[(bn + lrB) * D_MODEL + k0 + lcB]);
        float4 vb1 = *reinterpret_cast<const float4*>(&W[(bn + lrB) * D_MODEL + k0 + lcB + 4]);
        Bs[lcB + 0][lrB] = vb0.x; Bs[lcB + 1][lrB] = vb0.y;
        Bs[lcB + 2][lrB] = vb0.z; Bs[lcB + 3][lrB] = vb0.w;
        Bs[lcB + 4][lrB] = vb1.x; Bs[lcB + 5][lrB] = vb1.y;
        Bs[lcB + 6][lrB] = vb1.z; Bs[lcB + 7][lrB] = vb1.w;
        __syncthreads();
#pragma unroll
        for (int kk = 0; kk < 16; kk++) {
            float4 a = *reinterpret_cast<float4*>(&As[kk][ty * 4]);
            float4 b0 = *reinterpret_cast<float4*>(&Bs[kk][tx * 8]);
            float4 b1 = *reinterpret_cast<float4*>(&Bs[kk][tx * 8 + 4]);
            float av[4] = {a.x, a.y, a.z, a.w};
            float bv[8] = {b0.x, b0.y, b0.z, b0.w, b1.x, b1.y, b1.z, b1.w};
#pragma unroll
            for (int ii = 0; ii < 4; ii++)
#pragma unroll
                for (int jj = 0; jj < 8; jj++) acc[ii][jj] += av[ii] * bv[jj];
        }
        __syncthreads();
    }
    float bias8[8] = {};
    if (w == 0) {
        float4 b0 = *reinterpret_cast<const float4*>(&bq[bn + tx * 8]);
        float4 b1 = *reinterpret_cast<const float4*>(&bq[bn + tx * 8 + 4]);
        bias8[0] = b0.x; bias8[1] = b0.y; bias8[2] = b0.z; bias8[3] = b0.w;
        bias8[4] = b1.x; bias8[5] = b1.y; bias8[6] = b1.z; bias8[7] = b1.w;
    }
#pragma unroll
    for (int ii = 0; ii < 4; ii++) {
        float4 o0 = make_float4(acc[ii][0] + bias8[0], acc[ii][1] + bias8[1],
                                acc[ii][2] + bias8[2], acc[ii][3] + bias8[3]);
        float4 o1 = make_float4(acc[ii][4] + bias8[4], acc[ii][5] + bias8[5],
                                acc[ii][6] + bias8[6], acc[ii][7] + bias8[7]);
        *reinterpret_cast<float4*>(&C[(bm + ty * 4 + ii) * D_MODEL + bn + tx * 8]) = o0;
        *reinterpret_cast<float4*>(&C[(bm + ty * 4 + ii) * D_MODEL + bn + tx * 8 + 4]) = o1;
    }
}

// ---------------- K2: pair bias: LN(z) @ A^T via linearity trick ----------------
__global__ void bias_kernel(const float* __restrict__ z) {
    __shared__ float zs[64][132];
    __shared__ float As[16][132];
    __shared__ float mu[64], rs[64];
    int i = blockIdx.y;
    int j0 = blockIdx.x * 64;
    int tid = threadIdx.x;

    for (int t = tid; t < NH * CZ; t += 256) As[t >> 7][t & 127] = g_A[t];

    const float* zb = z + ((size_t)i * N_TOK + j0) * CZ;
#pragma unroll
    for (int it = 0; it < 8; it++) {
        int f4 = tid + it * 256;
        int r = f4 >> 5, c4 = f4 & 31;
        float4 v = *reinterpret_cast<const float4*>(zb + r * CZ + c4 * 4);
        *reinterpret_cast<float4*>(&zs[r][c4 * 4]) = v;
    }
    __syncthreads();

    if (tid < 64) {
        float sm = 0.f, sq = 0.f;
#pragma unroll 8
        for (int c4 = 0; c4 < 32; c4++) {
            float4 v = *reinterpret_cast<float4*>(&zs[tid][c4 * 4]);
            sm += v.x + v.y + v.z + v.w;
            sq += v.x * v.x + v.y * v.y + v.z * v.z + v.w * v.w;
        }
        float m = sm * (1.0f / CZ);
        float var = sq * (1.0f / CZ) - m * m;
        mu[tid] = m;
        rs[tid] = rsqrtf(var + LN_EPS);
    }
    __syncthreads();

    int lane = tid & 31;
    int h0 = (tid >> 5) * 2;
    float a00 = 0.f, a01 = 0.f, a10 = 0.f, a11 = 0.f;
#pragma unroll 8
    for (int c4 = 0; c4 < 32; c4++) {
        float4 z0 = *reinterpret_cast<float4*>(&zs[lane][c4 * 4]);
        float4 z1 = *reinterpret_cast<float4*>(&zs[lane + 32][c4 * 4]);
        float4 p0 = *reinterpret_cast<float4*>(&As[h0][c4 * 4]);
        float4 p1 = *reinterpret_cast<float4*>(&As[h0 + 1][c4 * 4]);
        a00 += z0.x * p0.x + z0.y * p0.y + z0.z * p0.z + z0.w * p0.w;
        a01 += z1.x * p0.x + z1.y * p0.y + z1.z * p0.z + z1.w * p0.w;
        a10 += z0.x * p1.x + z0.y * p1.y + z0.z * p1.z + z0.w * p1.w;
        a11 += z1.x * p1.x + z1.y * p1.y + z1.z * p1.z + z1.w * p1.w;
    }
    float m0 = mu[lane], r0 = rs[lane];
    float m1 = mu[lane + 32], r1 = rs[lane + 32];
    {
        float sa = g_SA[h0], cb = g_CB[h0];
        size_t base = ((size_t)h0 * N_TOK + i) * N_TOK + j0;
        g_bias[base + lane] = r0 * (a00 - m0 * sa) + cb;
        g_bias[base + lane + 32] = r1 * (a01 - m1 * sa) + cb;
    }
    {
        float sa = g_SA[h0 + 1], cb = g_CB[h0 + 1];
        size_t base = ((size_t)(h0 + 1) * N_TOK + i) * N_TOK + j0;
        g_bias[base + lane] = r0 * (a10 - m0 * sa) + cb;
        g_bias[base + lane + 32] = r1 * (a11 - m1 * sa) + cb;
    }
}

// ---------------- K3: fused flash attention (logits + softmax + AV) ----------------
// block = (i-tile 64, head). 256 threads; quad of 4 threads per query row.
// sub = tid&3: owns j-range sub*16.. for QK, and d-range sub*8.. for PV.
__global__ void flash_kernel() {
    __shared__ float Ks[64][36];
    __shared__ float Vs[64][36];
    __shared__ float Ps[64][68];
    int h = blockIdx.y;
    int i0 = blockIdx.x * 64;
    int tid = threadIdx.x;
    int r = tid >> 2;
    int sub = tid & 3;
    const float scale = 0.17677669529663687f;  // 32^-0.5

    float qreg[32];
    {
        const float* qp = &g_q[(i0 + r) * D_MODEL + h * DH];
#pragma unroll
        for (int d4 = 0; d4 < 8; d4++) {
            float4 v = *reinterpret_cast<const float4*>(qp + d4 * 4);
            qreg[d4 * 4 + 0] = v.x * scale; qreg[d4 * 4 + 1] = v.y * scale;
            qreg[d4 * 4 + 2] = v.z * scale; qreg[d4 * 4 + 3] = v.w * scale;
        }
    }

    float acc[8] = {};
    float m_run = -1e30f, l_run = 0.f;

    for (int j0 = 0; j0 < N_TOK; j0 += 64) {
        // load K,V tiles (row-major [j][d])
#pragma unroll
        for (int it = 0; it < 2; it++) {
            int e = tid + it * 256;  // over 512 float4 slots
            int j = e >> 3, d4 = e & 7;
            float4 kv = *reinterpret_cast<const float4*>(
                &g_k[(j0 + j) * D_MODEL + h * DH + d4 * 4]);
            float4 vv = *reinterpret_cast<const float4*>(
                &g_v[(j0 + j) * D_MODEL + h * DH + d4 * 4]);
            *reinterpret_cast<float4*>(&Ks[j][d4 * 4]) = kv;
            *reinterpret_cast<float4*>(&Vs[j][d4 * 4]) = vv;
        }
        __syncthreads();

        // logits for 16 j's: bias + q.k
        float lg[16];
        const float* bp = &g_bias[((size_t)h * N_TOK + i0 + r) * N_TOK + j0 + sub * 16];
#pragma unroll
        for (int jj4 = 0; jj4 < 4; jj4++) {
            float4 b4 = *reinterpret_cast<const float4*>(bp + jj4 * 4);
            lg[jj4 * 4 + 0] = b4.x; lg[jj4 * 4 + 1] = b4.y;
            lg[jj4 * 4 + 2] = b4.z; lg[jj4 * 4 + 3] = b4.w;
        }
#pragma unroll
        for (int jj = 0; jj < 16; jj++) {
            int j = sub * 16 + jj;
            float dot = 0.f;
#pragma unroll
            for (int d4 = 0; d4 < 8; d4++) {
                float4 k4 = *reinterpret_cast<float4*>(&Ks[j][d4 * 4]);
                dot += qreg[d4 * 4 + 0] * k4.x + qreg[d4 * 4 + 1] * k4.y +
                       qreg[d4 * 4 + 2] * k4.z + qreg[d4 * 4 + 3] * k4.w;
            }
            lg[jj] += dot;
        }
        // online softmax (quad = one row)
        float mx = lg[0];
#pragma unroll
        for (int jj = 1; jj < 16; jj++) mx = fmaxf(mx, lg[jj]);
        mx = fmaxf(mx, __shfl_xor_sync(0xffffffffu, mx, 1));
        mx = fmaxf(mx, __shfl_xor_sync(0xffffffffu, mx, 2));
        float m_new = fmaxf(m_run, mx);
        float corr = __expf(m_run - m_new);
        float ls = 0.f;
#pragma unroll
        for (int jj = 0; jj < 16; jj++) {
            float p = __expf(lg[jj] - m_new);
            ls += p;
            Ps[r][sub * 16 + jj] = p;
        }
        ls += __shfl_xor_sync(0xffffffffu, ls, 1);
        ls += __shfl_xor_sync(0xffffffffu, ls, 2);
        l_run = l_run * corr + ls;
        m_run = m_new;
#pragma unroll
        for (int d = 0; d < 8; d++) acc[d] *= corr;
        __syncwarp();
        // PV: acc[d-own] += sum_j p_j * V[j][d-own]
#pragma unroll
        for (int j4 = 0; j4 < 16; j4++) {
            float4 pv = *reinterpret_cast<float4*>(&Ps[r][j4 * 4]);
            float pj[4] = {pv.x, pv.y, pv.z, pv.w};
#pragma unroll
            for (int u = 0; u < 4; u++) {
                int j = j4 * 4 + u;
                float4 va = *reinterpret_cast<float4*>(&Vs[j][sub * 8]);
                float4 vb = *reinterpret_cast<float4*>(&Vs[j][sub * 8 + 4]);
                acc[0] += pj[u] * va.x; acc[1] += pj[u] * va.y;
                acc[2] += pj[u] * va.z; acc[3] += pj[u] * va.w;
                acc[4] += pj[u] * vb.x; acc[5] += pj[u] * vb.y;
                acc[6] += pj[u] * vb.z; acc[7] += pj[u] * vb.w;
            }
        }
        __syncthreads();
    }

    float inv = 1.0f / l_run;
    float* op = &g_o[(i0 + r) * D_MODEL + h * DH + sub * 8];
    float4 o0 = make_float4(acc[0] * inv, acc[1] * inv, acc[2] * inv, acc[3] * inv);
    float4 o1 = make_float4(acc[4] * inv, acc[5] * inv, acc[6] * inv, acc[7] * inv);
    *reinterpret_cast<float4*>(op) = o0;
    *reinterpret_cast<float4*>(op + 4) = o1;
}

// ---------------- K4: out = (o * sigmoid(g)) @ Wo^T ----------------
__global__ void out_kernel(const float* __restrict__ Wo, float* __restrict__ out) {
    __shared__ float As[16][68];
    __shared__ float Bs[16][68];
    int bm = blockIdx.y * 64, bn = blockIdx.x * 64;
    int tid = threadIdx.x;
    int tx = tid & 15, ty = tid >> 4;
    float acc[4][4] = {};
    int lr = tid >> 2;
    int lc = (tid & 3) * 4;

    for (int k0 = 0; k0 < D_MODEL; k0 += 16) {
        float4 va = *reinterpret_cast<const float4*>(&g_o[(bm + lr) * D_MODEL + k0 + lc]);
        float4 vg = *reinterpret_cast<const float4*>(&g_g[(bm + lr) * D_MODEL + k0 + lc]);
        float4 vb = *reinterpret_cast<const float4*>(&Wo[(bn + lr) * D_MODEL + k0 + lc]);
        va.x *= 1.0f / (1.0f + __expf(-vg.x));
        va.y *= 1.0f / (1.0f + __expf(-vg.y));
        va.z *= 1.0f / (1.0f + __expf(-vg.z));
        va.w *= 1.0f / (1.0f + __expf(-vg.w));
        As[lc + 0][lr] = va.x; As[lc + 1][lr] = va.y; As[lc + 2][lr] = va.z; As[lc + 3][lr] = va.w;
        Bs[lc + 0][lr] = vb.x; Bs[lc + 1][lr] = vb.y; Bs[lc + 2][lr] = vb.z; Bs[lc + 3][lr] = vb.w;
        __syncthreads();
#pragma unroll
        for (int kk = 0; kk < 16; kk++) {
            float4 a = *reinterpret_cast<float4*>(&As[kk][ty * 4]);
            float4 b = *reinterpret_cast<float4*>(&Bs[kk][tx * 4]);
            float av[4] = {a.x, a.y, a.z, a.w};
            float bv[4] = {b.x, b.y, b.z, b.w};
#pragma unroll
            for (int ii = 0; ii < 4; ii++)
#pragma unroll
                for (int jj = 0; jj < 4; jj++) acc[ii][jj] += av[ii] * bv[jj];
        }
        __syncthreads();
    }
#pragma unroll
    for (int ii = 0; ii < 4; ii++) {
        float4 o4 = make_float4(acc[ii][0], acc[ii][1], acc[ii][2], acc[ii][3]);
        *reinterpret_cast<float4*>(&out[(bm + ty * 4 + ii) * D_MODEL + bn + tx * 4]) = o4;
    }
}

// ---------------- launch ----------------
extern "C" void kernel_launch(void* const* d_in, const int* in_sizes, int n_in,
                              void* d_out, int out_size) {
    const float* s   = (const float*)d_in[0];
    const float* z   = (const float*)d_in[1];
    const float* Wq  = (const float*)d_in[2];
    const float* bq  = (const float*)d_in[3];
    const float* Wk  = (const float*)d_in[4];
    const float* Wv  = (const float*)d_in[5];
    const float* Wg  = (const float*)d_in[6];
    const float* Wo  = (const float*)d_in[7];
    const float* lnw = (const float*)d_in[8];
    const float* lnb = (const float*)d_in[9];
    const float* Wz  = (const float*)d_in[10];
    float* out = (float*)d_out;

    prep_kernel<<<1, 128>>>(Wz, lnw, lnb);
    proj_kernel<<<dim3(D_MODEL / 128, N_TOK / 64, 4), 256>>>(s, Wq, bq, Wk, Wv, Wg);
    bias_kernel<<<dim3(N_TOK / 64, N_TOK), 256>>>(z);
    flash_kernel<<<dim3(N_TOK / 64, NH), 256>>>();
    out_kernel<<<dim3(D_MODEL / 64, N_TOK / 64), 256>>>(Wo, out);
}

// round 3
// speedup vs baseline: 1.6367x; 1.6367x over previous
#include <cuda_runtime.h>
#include <math.h>

#define N_TOK 768
#define D_MODEL 512
#define CZ 128
#define NH 16
#define DH 32
#define LN_EPS 1e-5f

// ---------------- scratch ----------------
__device__ float g_q[N_TOK * D_MODEL];
__device__ float g_k[N_TOK * D_MODEL];
__device__ float g_v[N_TOK * D_MODEL];
__device__ float g_g[N_TOK * D_MODEL];
__device__ float g_o[N_TOK * D_MODEL];
__device__ float g_logits[(size_t)NH * N_TOK * N_TOK];  // bias -> logits -> attn (in place)
__device__ float g_A[NH * CZ];
__device__ float g_SA[NH];
__device__ float g_CB[NH];

// ---------------- K0: fold LN affine into Wz ----------------
__global__ void prep_kernel(const float* __restrict__ Wz,
                            const float* __restrict__ lnw,
                            const float* __restrict__ lnb) {
    __shared__ float red[8];
    int c = threadIdx.x;  // 128 threads
    float wc = lnw[c], bc = lnb[c];
    for (int h = 0; h < NH; h++) {
        float wz = Wz[h * CZ + c];
        float a = wz * wc;
        g_A[h * CZ + c] = a;
        float sa = a, cb = wz * bc;
        for (int o = 16; o; o >>= 1) {
            sa += __shfl_down_sync(0xffffffffu, sa, o);
            cb += __shfl_down_sync(0xffffffffu, cb, o);
        }
        if ((c & 31) == 0) { red[c >> 5] = sa; red[4 + (c >> 5)] = cb; }
        __syncthreads();
        if (c == 0) {
            g_SA[h] = red[0] + red[1] + red[2] + red[3];
            g_CB[h] = red[4] + red[5] + red[6] + red[7];
        }
        __syncthreads();
    }
}

// ---------------- K1: q,k,v,g projections: C = s @ W^T (+bias for q) ----------------
// BM=128, BN=64, BK=16, 256 threads, 8x4 per thread (32 FMA : 3 LDS.128)
__global__ void proj_kernel(const float* __restrict__ s,
                            const float* __restrict__ Wq, const float* __restrict__ bq,
                            const float* __restrict__ Wk, const float* __restrict__ Wv,
                            const float* __restrict__ Wg) {
    __shared__ float As[16][132];   // As[k][m] m=128
    __shared__ float Bs[16][68];    // Bs[k][n] n=64
    int w = blockIdx.z;
    const float* W = (w == 0) ? Wq : (w == 1) ? Wk : (w == 2) ? Wv : Wg;
    float* C = (w == 0) ? g_q : (w == 1) ? g_k : (w == 2) ? g_v : g_g;
    int bm = blockIdx.y * 128, bn = blockIdx.x * 64;
    int tid = threadIdx.x;
    int tx = tid & 15, ty = tid >> 4;   // tx: 16 x 4 cols, ty: 16 x 8 rows
    float acc[8][4] = {};

    for (int k0 = 0; k0 < D_MODEL; k0 += 16) {
        // load A: 128x16 = 512 float4, 2 per thread
#pragma unroll
        for (int it = 0; it < 2; it++) {
            int e = tid + it * 256;
            int r = e >> 2, c4 = (e & 3) * 4;
            float4 v = *reinterpret_cast<const float4*>(&s[(bm + r) * D_MODEL + k0 + c4]);
            As[c4 + 0][r] = v.x; As[c4 + 1][r] = v.y; As[c4 + 2][r] = v.z; As[c4 + 3][r] = v.w;
        }
        // load B: 64x16 = 256 float4, 1 per thread
        {
            int r = tid >> 2, c4 = (tid & 3) * 4;
            float4 v = *reinterpret_cast<const float4*>(&W[(bn + r) * D_MODEL + k0 + c4]);
            Bs[c4 + 0][r] = v.x; Bs[c4 + 1][r] = v.y; Bs[c4 + 2][r] = v.z; Bs[c4 + 3][r] = v.w;
        }
        __syncthreads();
#pragma unroll
        for (int kk = 0; kk < 16; kk++) {
            float4 a0 = *reinterpret_cast<float4*>(&As[kk][ty * 8]);
            float4 a1 = *reinterpret_cast<float4*>(&As[kk][ty * 8 + 4]);
            float4 b = *reinterpret_cast<float4*>(&Bs[kk][tx * 4]);
            float av[8] = {a0.x, a0.y, a0.z, a0.w, a1.x, a1.y, a1.z, a1.w};
            float bv[4] = {b.x, b.y, b.z, b.w};
#pragma unroll
            for (int ii = 0; ii < 8; ii++)
#pragma unroll
                for (int jj = 0; jj < 4; jj++) acc[ii][jj] += av[ii] * bv[jj];
        }
        __syncthreads();
    }
    float4 bias4 = make_float4(0.f, 0.f, 0.f, 0.f);
    if (w == 0) bias4 = *reinterpret_cast<const float4*>(&bq[bn + tx * 4]);
#pragma unroll
    for (int ii = 0; ii < 8; ii++) {
        float4 o4 = make_float4(acc[ii][0] + bias4.x, acc[ii][1] + bias4.y,
                                acc[ii][2] + bias4.z, acc[ii][3] + bias4.w);
        *reinterpret_cast<float4*>(&C[(bm + ty * 8 + ii) * D_MODEL + bn + tx * 4]) = o4;
    }
}

// ---------------- K2: pair bias: LN(z) @ A^T via linearity trick ----------------
__global__ void bias_kernel(const float* __restrict__ z) {
    __shared__ float zs[64][132];
    __shared__ float As[16][132];
    __shared__ float mu[64], rs[64];
    int i = blockIdx.y;
    int j0 = blockIdx.x * 64;
    int tid = threadIdx.x;

    for (int t = tid; t < NH * CZ; t += 256) As[t >> 7][t & 127] = g_A[t];

    const float* zb = z + ((size_t)i * N_TOK + j0) * CZ;
#pragma unroll
    for (int it = 0; it < 8; it++) {
        int f4 = tid + it * 256;
        int r = f4 >> 5, c4 = f4 & 31;
        float4 v = *reinterpret_cast<const float4*>(zb + r * CZ + c4 * 4);
        *reinterpret_cast<float4*>(&zs[r][c4 * 4]) = v;
    }
    __syncthreads();

    if (tid < 64) {
        float sm = 0.f, sq = 0.f;
#pragma unroll 8
        for (int c4 = 0; c4 < 32; c4++) {
            float4 v = *reinterpret_cast<float4*>(&zs[tid][c4 * 4]);
            sm += v.x + v.y + v.z + v.w;
            sq += v.x * v.x + v.y * v.y + v.z * v.z + v.w * v.w;
        }
        float m = sm * (1.0f / CZ);
        float var = sq * (1.0f / CZ) - m * m;
        mu[tid] = m;
        rs[tid] = rsqrtf(var + LN_EPS);
    }
    __syncthreads();

    int lane = tid & 31;
    int h0 = (tid >> 5) * 2;
    float a00 = 0.f, a01 = 0.f, a10 = 0.f, a11 = 0.f;
#pragma unroll 8
    for (int c4 = 0; c4 < 32; c4++) {
        float4 z0 = *reinterpret_cast<float4*>(&zs[lane][c4 * 4]);
        float4 z1 = *reinterpret_cast<float4*>(&zs[lane + 32][c4 * 4]);
        float4 p0 = *reinterpret_cast<float4*>(&As[h0][c4 * 4]);
        float4 p1 = *reinterpret_cast<float4*>(&As[h0 + 1][c4 * 4]);
        a00 += z0.x * p0.x + z0.y * p0.y + z0.z * p0.z + z0.w * p0.w;
        a01 += z1.x * p0.x + z1.y * p0.y + z1.z * p0.z + z1.w * p0.w;
        a10 += z0.x * p1.x + z0.y * p1.y + z0.z * p1.z + z0.w * p1.w;
        a11 += z1.x * p1.x + z1.y * p1.y + z1.z * p1.z + z1.w * p1.w;
    }
    float m0 = mu[lane], r0 = rs[lane];
    float m1 = mu[lane + 32], r1 = rs[lane + 32];
    {
        float sa = g_SA[h0], cb = g_CB[h0];
        size_t base = ((size_t)h0 * N_TOK + i) * N_TOK + j0;
        g_logits[base + lane] = r0 * (a00 - m0 * sa) + cb;
        g_logits[base + lane + 32] = r1 * (a01 - m1 * sa) + cb;
    }
    {
        float sa = g_SA[h0 + 1], cb = g_CB[h0 + 1];
        size_t base = ((size_t)(h0 + 1) * N_TOK + i) * N_TOK + j0;
        g_logits[base + lane] = r0 * (a10 - m0 * sa) + cb;
        g_logits[base + lane + 32] = r1 * (a11 - m1 * sa) + cb;
    }
}

// ---------------- K3a: logits += scale * Q K^T ----------------
__global__ void logits_kernel() {
    __shared__ float Qs[32][36];
    __shared__ float Ks[64][36];
    int h = blockIdx.z;
    int i0 = blockIdx.y * 32;
    int j0 = blockIdx.x * 64;
    int tid = threadIdx.x;
    {
        int r = tid >> 3, c4 = tid & 7;
        float4 v = *reinterpret_cast<const float4*>(&g_q[(i0 + r) * D_MODEL + h * DH + c4 * 4]);
        *reinterpret_cast<float4*>(&Qs[r][c4 * 4]) = v;
    }
#pragma unroll
    for (int it = 0; it < 2; it++) {
        int f4 = tid + it * 256;
        int r = f4 >> 3, c4 = f4 & 7;
        float4 v = *reinterpret_cast<const float4*>(&g_k[(j0 + r) * D_MODEL + h * DH + c4 * 4]);
        *reinterpret_cast<float4*>(&Ks[r][c4 * 4]) = v;
    }
    __syncthreads();
    int tx = tid & 15, ty = tid >> 4;
    float acc[2][4] = {};
#pragma unroll
    for (int d4 = 0; d4 < 8; d4++) {
        float4 q0 = *reinterpret_cast<float4*>(&Qs[ty * 2][d4 * 4]);
        float4 q1 = *reinterpret_cast<float4*>(&Qs[ty * 2 + 1][d4 * 4]);
#pragma unroll
        for (int m = 0; m < 4; m++) {
            float4 kv = *reinterpret_cast<float4*>(&Ks[tx + 16 * m][d4 * 4]);
            acc[0][m] += q0.x * kv.x + q0.y * kv.y + q0.z * kv.z + q0.w * kv.w;
            acc[1][m] += q1.x * kv.x + q1.y * kv.y + q1.z * kv.z + q1.w * kv.w;
        }
    }
    const float scale = 0.17677669529663687f;  // 32^-0.5
#pragma unroll
    for (int ii = 0; ii < 2; ii++)
#pragma unroll
        for (int m = 0; m < 4; m++) {
            size_t idx = ((size_t)h * N_TOK + i0 + ty * 2 + ii) * N_TOK + j0 + tx + 16 * m;
            g_logits[idx] = g_logits[idx] + acc[ii][m] * scale;
        }
}

// ---------------- K3b: row softmax ----------------
__global__ void softmax_kernel() {
    __shared__ float red[8];
    int i = blockIdx.x, h = blockIdx.y;
    float* row = &g_logits[((size_t)h * N_TOK + i) * N_TOK];
    int tid = threadIdx.x;
    float v0 = row[tid], v1 = row[tid + 256], v2 = row[tid + 512];
    float mx = fmaxf(v0, fmaxf(v1, v2));
    for (int o = 16; o; o >>= 1) mx = fmaxf(mx, __shfl_xor_sync(0xffffffffu, mx, o));
    if ((tid & 31) == 0) red[tid >> 5] = mx;
    __syncthreads();
    float m = red[0];
#pragma unroll
    for (int t = 1; t < 8; t++) m = fmaxf(m, red[t]);
    v0 = __expf(v0 - m); v1 = __expf(v1 - m); v2 = __expf(v2 - m);
    float sm = v0 + v1 + v2;
    for (int o = 16; o; o >>= 1) sm += __shfl_xor_sync(0xffffffffu, sm, o);
    __syncthreads();
    if ((tid & 31) == 0) red[tid >> 5] = sm;
    __syncthreads();
    float s = red[0];
#pragma unroll
    for (int t = 1; t < 8; t++) s += red[t];
    float inv = 1.0f / s;
    row[tid] = v0 * inv; row[tid + 256] = v1 * inv; row[tid + 512] = v2 * inv;
}

// ---------------- K3c: O = P @ V ----------------
__global__ void attnv_kernel() {
    __shared__ float Ps[64][68];
    __shared__ float Vs[32][68];  // transposed: Vs[d][j]
    int h = blockIdx.y;
    int i0 = blockIdx.x * 64;
    int tid = threadIdx.x;
    int tx = tid & 15, ty = tid >> 4;
    float acc[4][2] = {};
    for (int j0 = 0; j0 < N_TOK; j0 += 64) {
#pragma unroll
        for (int it = 0; it < 4; it++) {
            int f4 = tid + it * 256;
            int r = f4 >> 4, c4 = f4 & 15;
            float4 v = *reinterpret_cast<const float4*>(
                &g_logits[((size_t)h * N_TOK + i0 + r) * N_TOK + j0 + c4 * 4]);
            *reinterpret_cast<float4*>(&Ps[r][c4 * 4]) = v;
        }
#pragma unroll
        for (int it = 0; it < 8; it++) {
            int e = tid + it * 256;
            int r = e >> 5, d = e & 31;
            Vs[d][r] = g_v[(j0 + r) * D_MODEL + h * DH + d];
        }
        __syncthreads();
#pragma unroll 8
        for (int j4 = 0; j4 < 16; j4++) {
            float4 va = *reinterpret_cast<float4*>(&Vs[tx][j4 * 4]);
            float4 vb = *reinterpret_cast<float4*>(&Vs[tx + 16][j4 * 4]);
#pragma unroll
            for (int m = 0; m < 4; m++) {
                float4 p = *reinterpret_cast<float4*>(&Ps[ty + 16 * m][j4 * 4]);
                acc[m][0] += p.x * va.x + p.y * va.y + p.z * va.z + p.w * va.w;
                acc[m][1] += p.x * vb.x + p.y * vb.y + p.z * vb.z + p.w * vb.w;
            }
        }
        __syncthreads();
    }
#pragma unroll
    for (int m = 0; m < 4; m++) {
        g_o[(i0 + ty + 16 * m) * D_MODEL + h * DH + tx] = acc[m][0];
        g_o[(i0 + ty + 16 * m) * D_MODEL + h * DH + tx + 16] = acc[m][1];
    }
}

// ---------------- K4: out = (o * sigmoid(g)) @ Wo^T ----------------
__global__ void out_kernel(const float* __restrict__ Wo, float* __restrict__ out) {
    __shared__ float As[16][68];
    __shared__ float Bs[16][68];
    int bm = blockIdx.y * 64, bn = blockIdx.x * 64;
    int tid = threadIdx.x;
    int tx = tid & 15, ty = tid >> 4;
    float acc[4][4] = {};
    int lr = tid >> 2;
    int lc = (tid & 3) * 4;

    for (int k0 = 0; k0 < D_MODEL; k0 += 16) {
        float4 va = *reinterpret_cast<const float4*>(&g_o[(bm + lr) * D_MODEL + k0 + lc]);
        float4 vg = *reinterpret_cast<const float4*>(&g_g[(bm + lr) * D_MODEL + k0 + lc]);
        float4 vb = *reinterpret_cast<const float4*>(&Wo[(bn + lr) * D_MODEL + k0 + lc]);
        va.x *= 1.0f / (1.0f + __expf(-vg.x));
        va.y *= 1.0f / (1.0f + __expf(-vg.y));
        va.z *= 1.0f / (1.0f + __expf(-vg.z));
        va.w *= 1.0f / (1.0f + __expf(-vg.w));
        As[lc + 0][lr] = va.x; As[lc + 1][lr] = va.y; As[lc + 2][lr] = va.z; As[lc + 3][lr] = va.w;
        Bs[lc + 0][lr] = vb.x; Bs[lc + 1][lr] = vb.y; Bs[lc + 2][lr] = vb.z; Bs[lc + 3][lr] = vb.w;
        __syncthreads();
#pragma unroll
        for (int kk = 0; kk < 16; kk++) {
            float4 a = *reinterpret_cast<float4*>(&As[kk][ty * 4]);
            float4 b = *reinterpret_cast<float4*>(&Bs[kk][tx * 4]);
            float av[4] = {a.x, a.y, a.z, a.w};
            float bv[4] = {b.x, b.y, b.z, b.w};
#pragma unroll
            for (int ii = 0; ii < 4; ii++)
#pragma unroll
                for (int jj = 0; jj < 4; jj++) acc[ii][jj] += av[ii] * bv[jj];
        }
        __syncthreads();
    }
#pragma unroll
    for (int ii = 0; ii < 4; ii++) {
        float4 o4 = make_float4(acc[ii][0], acc[ii][1], acc[ii][2], acc[ii][3]);
        *reinterpret_cast<float4*>(&out[(bm + ty * 4 + ii) * D_MODEL + bn + tx * 4]) = o4;
    }
}

// ---------------- launch ----------------
extern "C" void kernel_launch(void* const* d_in, const int* in_sizes, int n_in,
                              void* d_out, int out_size) {
    const float* s   = (const float*)d_in[0];
    const float* z   = (const float*)d_in[1];
    const float* Wq  = (const float*)d_in[2];
    const float* bq  = (const float*)d_in[3];
    const float* Wk  = (const float*)d_in[4];
    const float* Wv  = (const float*)d_in[5];
    const float* Wg  = (const float*)d_in[6];
    const float* Wo  = (const float*)d_in[7];
    const float* lnw = (const float*)d_in[8];
    const float* lnb = (const float*)d_in[9];
    const float* Wz  = (const float*)d_in[10];
    float* out = (float*)d_out;

    prep_kernel<<<1, 128>>>(Wz, lnw, lnb);
    proj_kernel<<<dim3(D_MODEL / 64, N_TOK / 128, 4), 256>>>(s, Wq, bq, Wk, Wv, Wg);
    bias_kernel<<<dim3(N_TOK / 64, N_TOK), 256>>>(z);
    logits_kernel<<<dim3(N_TOK / 64, N_TOK / 32, NH), 256>>>();
    softmax_kernel<<<dim3(N_TOK, NH), 256>>>();
    attnv_kernel<<<dim3(N_TOK / 64, NH), 256>>>();
    out_kernel<<<dim3(D_MODEL / 64, N_TOK / 64), 256>>>(Wo, out);
}

// round 4
// speedup vs baseline: 1.8260x; 1.1157x over previous
#include <cuda_runtime.h>
#include <math.h>

#define N_TOK 768
#define D_MODEL 512
#define CZ 128
#define NH 16
#define DH 32
#define LN_EPS 1e-5f

// ---------------- scratch ----------------
__device__ float g_q[N_TOK * D_MODEL];
__device__ float g_k[N_TOK * D_MODEL];
__device__ float g_v[N_TOK * D_MODEL];
__device__ float g_g[N_TOK * D_MODEL];
__device__ float g_o[N_TOK * D_MODEL];
__device__ float g_logits[(size_t)NH * N_TOK * N_TOK];
__device__ float g_A[NH * CZ];
__device__ float g_SA[NH];
__device__ float g_CB[NH];

__device__ __forceinline__ unsigned f2tf32(float x) {
    unsigned r;
    asm("cvt.rna.tf32.f32 %0, %1;" : "=r"(r) : "f"(x));
    return r;
}

__device__ __forceinline__ void mma_tf32(float& d0, float& d1, float& d2, float& d3,
                                         unsigned a0, unsigned a1, unsigned a2, unsigned a3,
                                         unsigned b0, unsigned b1) {
    asm volatile(
        "mma.sync.aligned.m16n8k8.row.col.f32.tf32.tf32.f32 "
        "{%0,%1,%2,%3}, {%4,%5,%6,%7}, {%8,%9}, {%0,%1,%2,%3};"
        : "+f"(d0), "+f"(d1), "+f"(d2), "+f"(d3)
        : "r"(a0), "r"(a1), "r"(a2), "r"(a3), "r"(b0), "r"(b1));
}

// ---------------- K0: fold LN affine into Wz ----------------
__global__ void prep_kernel(const float* __restrict__ Wz,
                            const float* __restrict__ lnw,
                            const float* __restrict__ lnb) {
    __shared__ float red[8];
    int c = threadIdx.x;  // 128 threads
    float wc = lnw[c], bc = lnb[c];
    for (int h = 0; h < NH; h++) {
        float wz = Wz[h * CZ + c];
        float a = wz * wc;
        g_A[h * CZ + c] = a;
        float sa = a, cb = wz * bc;
        for (int o = 16; o; o >>= 1) {
            sa += __shfl_down_sync(0xffffffffu, sa, o);
            cb += __shfl_down_sync(0xffffffffu, cb, o);
        }
        if ((c & 31) == 0) { red[c >> 5] = sa; red[4 + (c >> 5)] = cb; }
        __syncthreads();
        if (c == 0) {
            g_SA[h] = red[0] + red[1] + red[2] + red[3];
            g_CB[h] = red[4] + red[5] + red[6] + red[7];
        }
        __syncthreads();
    }
}

// ---------------- K1: q,k,v,g projections ----------------
__global__ void proj_kernel(const float* __restrict__ s,
                            const float* __restrict__ Wq, const float* __restrict__ bq,
                            const float* __restrict__ Wk, const float* __restrict__ Wv,
                            const float* __restrict__ Wg) {
    __shared__ float As[16][132];
    __shared__ float Bs[16][68];
    int w = blockIdx.z;
    const float* W = (w == 0) ? Wq : (w == 1) ? Wk : (w == 2) ? Wv : Wg;
    float* C = (w == 0) ? g_q : (w == 1) ? g_k : (w == 2) ? g_v : g_g;
    int bm = blockIdx.y * 128, bn = blockIdx.x * 64;
    int tid = threadIdx.x;
    int tx = tid & 15, ty = tid >> 4;
    float acc[8][4] = {};

    for (int k0 = 0; k0 < D_MODEL; k0 += 16) {
#pragma unroll
        for (int it = 0; it < 2; it++) {
            int e = tid + it * 256;
            int r = e >> 2, c4 = (e & 3) * 4;
            float4 v = *reinterpret_cast<const float4*>(&s[(bm + r) * D_MODEL + k0 + c4]);
            As[c4 + 0][r] = v.x; As[c4 + 1][r] = v.y; As[c4 + 2][r] = v.z; As[c4 + 3][r] = v.w;
        }
        {
            int r = tid >> 2, c4 = (tid & 3) * 4;
            float4 v = *reinterpret_cast<const float4*>(&W[(bn + r) * D_MODEL + k0 + c4]);
            Bs[c4 + 0][r] = v.x; Bs[c4 + 1][r] = v.y; Bs[c4 + 2][r] = v.z; Bs[c4 + 3][r] = v.w;
        }
        __syncthreads();
#pragma unroll
        for (int kk = 0; kk < 16; kk++) {
            float4 a0 = *reinterpret_cast<float4*>(&As[kk][ty * 8]);
            float4 a1 = *reinterpret_cast<float4*>(&As[kk][ty * 8 + 4]);
            float4 b = *reinterpret_cast<float4*>(&Bs[kk][tx * 4]);
            float av[8] = {a0.x, a0.y, a0.z, a0.w, a1.x, a1.y, a1.z, a1.w};
            float bv[4] = {b.x, b.y, b.z, b.w};
#pragma unroll
            for (int ii = 0; ii < 8; ii++)
#pragma unroll
                for (int jj = 0; jj < 4; jj++) acc[ii][jj] += av[ii] * bv[jj];
        }
        __syncthreads();
    }
    float4 bias4 = make_float4(0.f, 0.f, 0.f, 0.f);
    if (w == 0) bias4 = *reinterpret_cast<const float4*>(&bq[bn + tx * 4]);
#pragma unroll
    for (int ii = 0; ii < 8; ii++) {
        float4 o4 = make_float4(acc[ii][0] + bias4.x, acc[ii][1] + bias4.y,
                                acc[ii][2] + bias4.z, acc[ii][3] + bias4.w);
        *reinterpret_cast<float4*>(&C[(bm + ty * 8 + ii) * D_MODEL + bn + tx * 4]) = o4;
    }
}

// ---------------- K2: pair bias via tf32 MMA + LN linearity ----------------
// block: (j-tile 64, i). 256 threads = 8 warps.
// warp w: m-tile (w&3) covers 16 j's; n-tile (w>>2) covers 8 heads; K=128 in 16 mma steps.
__global__ void bias_kernel(const float* __restrict__ z) {
    __shared__ float zs[64][132];
    __shared__ float As[16][132];
    __shared__ float mu_s[64], rs_s[64];
    int i = blockIdx.y;
    int j0 = blockIdx.x * 64;
    int tid = threadIdx.x;

    // load A (16x128) -> smem
    for (int e = tid; e < 16 * 32; e += 256) {
        int h = e >> 5, c4 = (e & 31) * 4;
        float4 v = *reinterpret_cast<const float4*>(&g_A[h * CZ + c4]);
        *reinterpret_cast<float4*>(&As[h][c4]) = v;
    }
    // stage z tile (64x128)
    const float* zb = z + ((size_t)i * N_TOK + j0) * CZ;
#pragma unroll
    for (int it = 0; it < 8; it++) {
        int f4 = tid + it * 256;
        int r = f4 >> 5, c4 = f4 & 31;
        float4 v = *reinterpret_cast<const float4*>(zb + r * CZ + c4 * 4);
        *reinterpret_cast<float4*>(&zs[r][c4 * 4]) = v;
    }
    __syncthreads();

    // stats: 4 threads per row, each 32 cols, quad-reduce
    {
        int row = tid >> 2, sub = tid & 3;
        float sm = 0.f, sq = 0.f;
#pragma unroll
        for (int c4 = 0; c4 < 8; c4++) {
            float4 v = *reinterpret_cast<float4*>(&zs[row][(sub * 8 + c4) * 4]);
            sm += v.x + v.y + v.z + v.w;
            sq += v.x * v.x + v.y * v.y + v.z * v.z + v.w * v.w;
        }
        sm += __shfl_xor_sync(0xffffffffu, sm, 1);
        sm += __shfl_xor_sync(0xffffffffu, sm, 2);
        sq += __shfl_xor_sync(0xffffffffu, sq, 1);
        sq += __shfl_xor_sync(0xffffffffu, sq, 2);
        if (sub == 0) {
            float m = sm * (1.0f / CZ);
            float var = sq * (1.0f / CZ) - m * m;
            mu_s[row] = m;
            rs_s[row] = rsqrtf(var + LN_EPS);
        }
    }
    __syncthreads();

    int w = tid >> 5, lane = tid & 31;
    int mtile = w & 3, ntile = w >> 2;
    int gr = lane >> 2, tig = lane & 3;

    const float* zr0 = &zs[mtile * 16 + gr][0];
    const float* zr1 = &zs[mtile * 16 + gr + 8][0];
    const float* ar = &As[ntile * 8 + gr][0];

    float d0 = 0.f, d1 = 0.f, d2 = 0.f, d3 = 0.f;
#pragma unroll
    for (int k0 = 0; k0 < CZ; k0 += 8) {
        unsigned a0 = f2tf32(zr0[k0 + tig]);
        unsigned a1 = f2tf32(zr1[k0 + tig]);
        unsigned a2 = f2tf32(zr0[k0 + tig + 4]);
        unsigned a3 = f2tf32(zr1[k0 + tig + 4]);
        unsigned b0 = f2tf32(ar[k0 + tig]);
        unsigned b1 = f2tf32(ar[k0 + tig + 4]);
        mma_tf32(d0, d1, d2, d3, a0, a1, a2, a3, b0, b1);
    }

    // epilogue: logits[h][i][j] = rs[j]*(d - mu[j]*SA[h]) + CB[h]
    int jl = mtile * 16 + gr;       // local j (row) for d0,d1
    int jh = jl + 8;                // for d2,d3
    int h0 = ntile * 8 + 2 * tig, h1 = h0 + 1;
    float mu_l = mu_s[jl], rs_l = rs_s[jl];
    float mu_h = mu_s[jh], rs_h = rs_s[jh];
    float sa0 = g_SA[h0], cb0 = g_CB[h0];
    float sa1 = g_SA[h1], cb1 = g_CB[h1];
    g_logits[((size_t)h0 * N_TOK + i) * N_TOK + j0 + jl] = rs_l * (d0 - mu_l * sa0) + cb0;
    g_logits[((size_t)h1 * N_TOK + i) * N_TOK + j0 + jl] = rs_l * (d1 - mu_l * sa1) + cb1;
    g_logits[((size_t)h0 * N_TOK + i) * N_TOK + j0 + jh] = rs_h * (d2 - mu_h * sa0) + cb0;
    g_logits[((size_t)h1 * N_TOK + i) * N_TOK + j0 + jh] = rs_h * (d3 - mu_h * sa1) + cb1;
}

// ---------------- K3a: logits += scale * Q K^T ----------------
__global__ void logits_kernel() {
    __shared__ float Qs[32][36];
    __shared__ float Ks[64][36];
    int h = blockIdx.z;
    int i0 = blockIdx.y * 32;
    int j0 = blockIdx.x * 64;
    int tid = threadIdx.x;
    {
        int r = tid >> 3, c4 = tid & 7;
        float4 v = *reinterpret_cast<const float4*>(&g_q[(i0 + r) * D_MODEL + h * DH + c4 * 4]);
        *reinterpret_cast<float4*>(&Qs[r][c4 * 4]) = v;
    }
#pragma unroll
    for (int it = 0; it < 2; it++) {
        int f4 = tid + it * 256;
        int r = f4 >> 3, c4 = f4 & 7;
        float4 v = *reinterpret_cast<const float4*>(&g_k[(j0 + r) * D_MODEL + h * DH + c4 * 4]);
        *reinterpret_cast<float4*>(&Ks[r][c4 * 4]) = v;
    }
    __syncthreads();
    int tx = tid & 15, ty = tid >> 4;
    float acc[2][4] = {};
#pragma unroll
    for (int d4 = 0; d4 < 8; d4++) {
        float4 q0 = *reinterpret_cast<float4*>(&Qs[ty * 2][d4 * 4]);
        float4 q1 = *reinterpret_cast<float4*>(&Qs[ty * 2 + 1][d4 * 4]);
#pragma unroll
        for (int m = 0; m < 4; m++) {
            float4 kv = *reinterpret_cast<float4*>(&Ks[tx + 16 * m][d4 * 4]);
            acc[0][m] += q0.x * kv.x + q0.y * kv.y + q0.z * kv.z + q0.w * kv.w;
            acc[1][m] += q1.x * kv.x + q1.y * kv.y + q1.z * kv.z + q1.w * kv.w;
        }
    }
    const float scale = 0.17677669529663687f;
#pragma unroll
    for (int ii = 0; ii < 2; ii++)
#pragma unroll
        for (int m = 0; m < 4; m++) {
            size_t idx = ((size_t)h * N_TOK + i0 + ty * 2 + ii) * N_TOK + j0 + tx + 16 * m;
            g_logits[idx] = g_logits[idx] + acc[ii][m] * scale;
        }
}

// ---------------- K3b: row softmax ----------------
__global__ void softmax_kernel() {
    __shared__ float red[8];
    int i = blockIdx.x, h = blockIdx.y;
    float* row = &g_logits[((size_t)h * N_TOK + i) * N_TOK];
    int tid = threadIdx.x;
    float v0 = row[tid], v1 = row[tid + 256], v2 = row[tid + 512];
    float mx = fmaxf(v0, fmaxf(v1, v2));
    for (int o = 16; o; o >>= 1) mx = fmaxf(mx, __shfl_xor_sync(0xffffffffu, mx, o));
    if ((tid & 31) == 0) red[tid >> 5] = mx;
    __syncthreads();
    float m = red[0];
#pragma unroll
    for (int t = 1; t < 8; t++) m = fmaxf(m, red[t]);
    v0 = __expf(v0 - m); v1 = __expf(v1 - m); v2 = __expf(v2 - m);
    float sm = v0 + v1 + v2;
    for (int o = 16; o; o >>= 1) sm += __shfl_xor_sync(0xffffffffu, sm, o);
    __syncthreads();
    if ((tid & 31) == 0) red[tid >> 5] = sm;
    __syncthreads();
    float s = red[0];
#pragma unroll
    for (int t = 1; t < 8; t++) s += red[t];
    float inv = 1.0f / s;
    row[tid] = v0 * inv; row[tid + 256] = v1 * inv; row[tid + 512] = v2 * inv;
}

// ---------------- K3c: O = P @ V ----------------
__global__ void attnv_kernel() {
    __shared__ float Ps[64][68];
    __shared__ float Vs[32][68];
    int h = blockIdx.y;
    int i0 = blockIdx.x * 64;
    int tid = threadIdx.x;
    int tx = tid & 15, ty = tid >> 4;
    float acc[4][2] = {};
    for (int j0 = 0; j0 < N_TOK; j0 += 64) {
#pragma unroll
        for (int it = 0; it < 4; it++) {
            int f4 = tid + it * 256;
            int r = f4 >> 4, c4 = f4 & 15;
            float4 v = *reinterpret_cast<const float4*>(
                &g_logits[((size_t)h * N_TOK + i0 + r) * N_TOK + j0 + c4 * 4]);
            *reinterpret_cast<float4*>(&Ps[r][c4 * 4]) = v;
        }
#pragma unroll
        for (int it = 0; it < 8; it++) {
            int e = tid + it * 256;
            int r = e >> 5, d = e & 31;
            Vs[d][r] = g_v[(j0 + r) * D_MODEL + h * DH + d];
        }
        __syncthreads();
#pragma unroll 8
        for (int j4 = 0; j4 < 16; j4++) {
            float4 va = *reinterpret_cast<float4*>(&Vs[tx][j4 * 4]);
            float4 vb = *reinterpret_cast<float4*>(&Vs[tx + 16][j4 * 4]);
#pragma unroll
            for (int m = 0; m < 4; m++) {
                float4 p = *reinterpret_cast<float4*>(&Ps[ty + 16 * m][j4 * 4]);
                acc[m][0] += p.x * va.x + p.y * va.y + p.z * va.z + p.w * va.w;
                acc[m][1] += p.x * vb.x + p.y * vb.y + p.z * vb.z + p.w * vb.w;
            }
        }
        __syncthreads();
    }
#pragma unroll
    for (int m = 0; m < 4; m++) {
        g_o[(i0 + ty + 16 * m) * D_MODEL + h * DH + tx] = acc[m][0];
        g_o[(i0 + ty + 16 * m) * D_MODEL + h * DH + tx + 16] = acc[m][1];
    }
}

// ---------------- K4: out = (o * sigmoid(g)) @ Wo^T ----------------
__global__ void out_kernel(const float* __restrict__ Wo, float* __restrict__ out) {
    __shared__ float As[16][68];
    __shared__ float Bs[16][68];
    int bm = blockIdx.y * 64, bn = blockIdx.x * 64;
    int tid = threadIdx.x;
    int tx = tid & 15, ty = tid >> 4;
    float acc[4][4] = {};
    int lr = tid >> 2;
    int lc = (tid & 3) * 4;

    for (int k0 = 0; k0 < D_MODEL; k0 += 16) {
        float4 va = *reinterpret_cast<const float4*>(&g_o[(bm + lr) * D_MODEL + k0 + lc]);
        float4 vg = *reinterpret_cast<const float4*>(&g_g[(bm + lr) * D_MODEL + k0 + lc]);
        float4 vb = *reinterpret_cast<const float4*>(&Wo[(bn + lr) * D_MODEL + k0 + lc]);
        va.x *= 1.0f / (1.0f + __expf(-vg.x));
        va.y *= 1.0f / (1.0f + __expf(-vg.y));
        va.z *= 1.0f / (1.0f + __expf(-vg.z));
        va.w *= 1.0f / (1.0f + __expf(-vg.w));
        As[lc + 0][lr] = va.x; As[lc + 1][lr] = va.y; As[lc + 2][lr] = va.z; As[lc + 3][lr] = va.w;
        Bs[lc + 0][lr] = vb.x; Bs[lc + 1][lr] = vb.y; Bs[lc + 2][lr] = vb.z; Bs[lc + 3][lr] = vb.w;
        __syncthreads();
#pragma unroll
        for (int kk = 0; kk < 16; kk++) {
            float4 a = *reinterpret_cast<float4*>(&As[kk][ty * 4]);
            float4 b = *reinterpret_cast<float4*>(&Bs[kk][tx * 4]);
            float av[4] = {a.x, a.y, a.z, a.w};
            float bv[4] = {b.x, b.y, b.z, b.w};
#pragma unroll
            for (int ii = 0; ii < 4; ii++)
#pragma unroll
                for (int jj = 0; jj < 4; jj++) acc[ii][jj] += av[ii] * bv[jj];
        }
        __syncthreads();
    }
#pragma unroll
    for (int ii = 0; ii < 4; ii++) {
        float4 o4 = make_float4(acc[ii][0], acc[ii][1], acc[ii][2], acc[ii][3]);
        *reinterpret_cast<float4*>(&out[(bm + ty * 4 + ii) * D_MODEL + bn + tx * 4]) = o4;
    }
}

// ---------------- launch ----------------
extern "C" void kernel_launch(void* const* d_in, const int* in_sizes, int n_in,
                              void* d_out, int out_size) {
    const float* s   = (const float*)d_in[0];
    const float* z   = (const float*)d_in[1];
    const float* Wq  = (const float*)d_in[2];
    const float* bq  = (const float*)d_in[3];
    const float* Wk  = (const float*)d_in[4];
    const float* Wv  = (const float*)d_in[5];
    const float* Wg  = (const float*)d_in[6];
    const float* Wo  = (const float*)d_in[7];
    const float* lnw = (const float*)d_in[8];
    const float* lnb = (const float*)d_in[9];
    const float* Wz  = (const float*)d_in[10];
    float* out = (float*)d_out;

    prep_kernel<<<1, 128>>>(Wz, lnw, lnb);
    proj_kernel<<<dim3(D_MODEL / 64, N_TOK / 128, 4), 256>>>(s, Wq, bq, Wk, Wv, Wg);
    bias_kernel<<<dim3(N_TOK / 64, N_TOK), 256>>>(z);
    logits_kernel<<<dim3(N_TOK / 64, N_TOK / 32, NH), 256>>>();
    softmax_kernel<<<dim3(N_TOK, NH), 256>>>();
    attnv_kernel<<<dim3(N_TOK / 64, NH), 256>>>();
    out_kernel<<<dim3(D_MODEL / 64, N_TOK / 64), 256>>>(Wo, out);
}

// round 5
// speedup vs baseline: 2.0315x; 1.1125x over previous
#include <cuda_runtime.h>
#include <math.h>

#define N_TOK 768
#define D_MODEL 512
#define CZ 128
#define NH 16
#define DH 32
#define LN_EPS 1e-5f

// ---------------- scratch ----------------
__device__ float g_q[N_TOK * D_MODEL];
__device__ float g_k[N_TOK * D_MODEL];
__device__ float g_v[N_TOK * D_MODEL];
__device__ float g_g[N_TOK * D_MODEL];
__device__ float g_o[N_TOK * D_MODEL];
__device__ float g_logits[(size_t)NH * N_TOK * N_TOK];
__device__ float g_A[NH * CZ];
__device__ float g_SA[NH];
__device__ float g_CB[NH];

__device__ __forceinline__ unsigned f2tf32(float x) {
    unsigned r;
    asm("cvt.rna.tf32.f32 %0, %1;" : "=r"(r) : "f"(x));
    return r;
}

__device__ __forceinline__ void mma_tf32(float* d,
                                         unsigned a0, unsigned a1, unsigned a2, unsigned a3,
                                         unsigned b0, unsigned b1) {
    asm volatile(
        "mma.sync.aligned.m16n8k8.row.col.f32.tf32.tf32.f32 "
        "{%0,%1,%2,%3}, {%4,%5,%6,%7}, {%8,%9}, {%0,%1,%2,%3};"
        : "+f"(d[0]), "+f"(d[1]), "+f"(d[2]), "+f"(d[3])
        : "r"(a0), "r"(a1), "r"(a2), "r"(a3), "r"(b0), "r"(b1));
}

// ---------------- K0: fold LN affine into Wz ----------------
__global__ void prep_kernel(const float* __restrict__ Wz,
                            const float* __restrict__ lnw,
                            const float* __restrict__ lnb) {
    __shared__ float red[8];
    int c = threadIdx.x;  // 128 threads
    float wc = lnw[c], bc = lnb[c];
    for (int h = 0; h < NH; h++) {
        float wz = Wz[h * CZ + c];
        float a = wz * wc;
        g_A[h * CZ + c] = a;
        float sa = a, cb = wz * bc;
        for (int o = 16; o; o >>= 1) {
            sa += __shfl_down_sync(0xffffffffu, sa, o);
            cb += __shfl_down_sync(0xffffffffu, cb, o);
        }
        if ((c & 31) == 0) { red[c >> 5] = sa; red[4 + (c >> 5)] = cb; }
        __syncthreads();
        if (c == 0) {
            g_SA[h] = red[0] + red[1] + red[2] + red[3];
            g_CB[h] = red[4] + red[5] + red[6] + red[7];
        }
        __syncthreads();
    }
}

// ---------------- K1: q,k,v,g projections via tf32 MMA ----------------
// block 256 thr = 8 warps; tile M=128 (rows of s), N=64 (out features), K=512.
// warp: mtile=w&3 (32 m), ntile=w>>2 (32 n); frags: 2m x 4n.
__global__ void proj_kernel(const float* __restrict__ s,
                            const float* __restrict__ Wq, const float* __restrict__ bq,
                            const float* __restrict__ Wk, const float* __restrict__ Wv,
                            const float* __restrict__ Wg) {
    __shared__ float ss[128][20];
    __shared__ float ws[64][20];
    int w = blockIdx.z;
    const float* W = (w == 0) ? Wq : (w == 1) ? Wk : (w == 2) ? Wv : Wg;
    float* C = (w == 0) ? g_q : (w == 1) ? g_k : (w == 2) ? g_v : g_g;
    int bm = blockIdx.y * 128, bn = blockIdx.x * 64;
    int tid = threadIdx.x;
    int wid = tid >> 5, lane = tid & 31;
    int mtile = wid & 3, ntile = wid >> 2;
    int gr = lane >> 2, tig = lane & 3;
    float acc[2][4][4] = {};

    for (int k0 = 0; k0 < D_MODEL; k0 += 16) {
#pragma unroll
        for (int it = 0; it < 2; it++) {
            int e = tid + it * 256;
            int r = e >> 2, c4 = (e & 3) * 4;
            float4 v = *reinterpret_cast<const float4*>(&s[(bm + r) * D_MODEL + k0 + c4]);
            *reinterpret_cast<float4*>(&ss[r][c4]) = v;
        }
        {
            int r = tid >> 2, c4 = (tid & 3) * 4;
            float4 v = *reinterpret_cast<const float4*>(&W[(bn + r) * D_MODEL + k0 + c4]);
            *reinterpret_cast<float4*>(&ws[r][c4]) = v;
        }
        __syncthreads();
#pragma unroll
        for (int kk = 0; kk < 16; kk += 8) {
            unsigned a[2][4];
#pragma unroll
            for (int mi = 0; mi < 2; mi++) {
                int mr = mtile * 32 + mi * 16 + gr;
                a[mi][0] = f2tf32(ss[mr][kk + tig]);
                a[mi][1] = f2tf32(ss[mr + 8][kk + tig]);
                a[mi][2] = f2tf32(ss[mr][kk + tig + 4]);
                a[mi][3] = f2tf32(ss[mr + 8][kk + tig + 4]);
            }
#pragma unroll
            for (int ni = 0; ni < 4; ni++) {
                int nr = ntile * 32 + ni * 8 + gr;
                unsigned b0 = f2tf32(ws[nr][kk + tig]);
                unsigned b1 = f2tf32(ws[nr][kk + tig + 4]);
#pragma unroll
                for (int mi = 0; mi < 2; mi++)
                    mma_tf32(acc[mi][ni], a[mi][0], a[mi][1], a[mi][2], a[mi][3], b0, b1);
            }
        }
        __syncthreads();
    }
#pragma unroll
    for (int mi = 0; mi < 2; mi++) {
#pragma unroll
        for (int ni = 0; ni < 4; ni++) {
            int m = bm + mtile * 32 + mi * 16 + gr;
            int n = bn + ntile * 32 + ni * 8 + 2 * tig;
            float b0 = 0.f, b1 = 0.f;
            if (w == 0) { b0 = bq[n]; b1 = bq[n + 1]; }
            *reinterpret_cast<float2*>(&C[m * D_MODEL + n]) =
                make_float2(acc[mi][ni][0] + b0, acc[mi][ni][1] + b1);
            *reinterpret_cast<float2*>(&C[(m + 8) * D_MODEL + n]) =
                make_float2(acc[mi][ni][2] + b0, acc[mi][ni][3] + b1);
        }
    }
}

// ---------------- K2: pair bias via tf32 MMA + LN linearity ----------------
__global__ void bias_kernel(const float* __restrict__ z) {
    __shared__ float zs[64][132];
    __shared__ float As[16][132];
    __shared__ float mu_s[64], rs_s[64];
    int i = blockIdx.y;
    int j0 = blockIdx.x * 64;
    int tid = threadIdx.x;

    for (int e = tid; e < 16 * 32; e += 256) {
        int h = e >> 5, c4 = (e & 31) * 4;
        float4 v = *reinterpret_cast<const float4*>(&g_A[h * CZ + c4]);
        *reinterpret_cast<float4*>(&As[h][c4]) = v;
    }
    const float* zb = z + ((size_t)i * N_TOK + j0) * CZ;
#pragma unroll
    for (int it = 0; it < 8; it++) {
        int f4 = tid + it * 256;
        int r = f4 >> 5, c4 = f4 & 31;
        float4 v = *reinterpret_cast<const float4*>(zb + r * CZ + c4 * 4);
        *reinterpret_cast<float4*>(&zs[r][c4 * 4]) = v;
    }
    __syncthreads();

    {
        int row = tid >> 2, sub = tid & 3;
        float sm = 0.f, sq = 0.f;
#pragma unroll
        for (int c4 = 0; c4 < 8; c4++) {
            float4 v = *reinterpret_cast<float4*>(&zs[row][(sub * 8 + c4) * 4]);
            sm += v.x + v.y + v.z + v.w;
            sq += v.x * v.x + v.y * v.y + v.z * v.z + v.w * v.w;
        }
        sm += __shfl_xor_sync(0xffffffffu, sm, 1);
        sm += __shfl_xor_sync(0xffffffffu, sm, 2);
        sq += __shfl_xor_sync(0xffffffffu, sq, 1);
        sq += __shfl_xor_sync(0xffffffffu, sq, 2);
        if (sub == 0) {
            float m = sm * (1.0f / CZ);
            float var = sq * (1.0f / CZ) - m * m;
            mu_s[row] = m;
            rs_s[row] = rsqrtf(var + LN_EPS);
        }
    }
    __syncthreads();

    int w = tid >> 5, lane = tid & 31;
    int mtile = w & 3, ntile = w >> 2;
    int gr = lane >> 2, tig = lane & 3;

    const float* zr0 = &zs[mtile * 16 + gr][0];
    const float* zr1 = &zs[mtile * 16 + gr + 8][0];
    const float* ar = &As[ntile * 8 + gr][0];

    float d[4] = {};
#pragma unroll
    for (int k0 = 0; k0 < CZ; k0 += 8) {
        unsigned a0 = f2tf32(zr0[k0 + tig]);
        unsigned a1 = f2tf32(zr1[k0 + tig]);
        unsigned a2 = f2tf32(zr0[k0 + tig + 4]);
        unsigned a3 = f2tf32(zr1[k0 + tig + 4]);
        unsigned b0 = f2tf32(ar[k0 + tig]);
        unsigned b1 = f2tf32(ar[k0 + tig + 4]);
        mma_tf32(d, a0, a1, a2, a3, b0, b1);
    }

    int jl = mtile * 16 + gr;
    int jh = jl + 8;
    int h0 = ntile * 8 + 2 * tig, h1 = h0 + 1;
    float mu_l = mu_s[jl], rs_l = rs_s[jl];
    float mu_h = mu_s[jh], rs_h = rs_s[jh];
    float sa0 = g_SA[h0], cb0 = g_CB[h0];
    float sa1 = g_SA[h1], cb1 = g_CB[h1];
    g_logits[((size_t)h0 * N_TOK + i) * N_TOK + j0 + jl] = rs_l * (d[0] - mu_l * sa0) + cb0;
    g_logits[((size_t)h1 * N_TOK + i) * N_TOK + j0 + jl] = rs_l * (d[1] - mu_l * sa1) + cb1;
    g_logits[((size_t)h0 * N_TOK + i) * N_TOK + j0 + jh] = rs_h * (d[2] - mu_h * sa0) + cb0;
    g_logits[((size_t)h1 * N_TOK + i) * N_TOK + j0 + jh] = rs_h * (d[3] - mu_h * sa1) + cb1;
}

// ---------------- K3a: logits += scale * Q K^T (tf32 MMA, RMW epilogue) ----------------
// block 256 thr; tile i=64, j=64, one head. warp: mtile=w&3 (16 i), ntile=w>>2 (32 j).
__global__ void logits_kernel() {
    __shared__ float qs[64][36];
    __shared__ float ks[64][36];
    int h = blockIdx.z;
    int i0 = blockIdx.y * 64;
    int j0 = blockIdx.x * 64;
    int tid = threadIdx.x;
    const float scale = 0.17677669529663687f;
#pragma unroll
    for (int it = 0; it < 2; it++) {
        int e = tid + it * 256;
        int r = e >> 3, c4 = (e & 7) * 4;
        float4 q = *reinterpret_cast<const float4*>(&g_q[(i0 + r) * D_MODEL + h * DH + c4]);
        q.x *= scale; q.y *= scale; q.z *= scale; q.w *= scale;
        *reinterpret_cast<float4*>(&qs[r][c4]) = q;
        float4 k = *reinterpret_cast<const float4*>(&g_k[(j0 + r) * D_MODEL + h * DH + c4]);
        *reinterpret_cast<float4*>(&ks[r][c4]) = k;
    }
    __syncthreads();

    int wid = tid >> 5, lane = tid & 31;
    int mtile = wid & 3, ntile = wid >> 2;
    int gr = lane >> 2, tig = lane & 3;
    float acc[4][4] = {};
#pragma unroll
    for (int kk = 0; kk < DH; kk += 8) {
        int mr = mtile * 16 + gr;
        unsigned a0 = f2tf32(qs[mr][kk + tig]);
        unsigned a1 = f2tf32(qs[mr + 8][kk + tig]);
        unsigned a2 = f2tf32(qs[mr][kk + tig + 4]);
        unsigned a3 = f2tf32(qs[mr + 8][kk + tig + 4]);
#pragma unroll
        for (int ni = 0; ni < 4; ni++) {
            int nr = ntile * 32 + ni * 8 + gr;
            unsigned b0 = f2tf32(ks[nr][kk + tig]);
            unsigned b1 = f2tf32(ks[nr][kk + tig + 4]);
            mma_tf32(acc[ni], a0, a1, a2, a3, b0, b1);
        }
    }
#pragma unroll
    for (int ni = 0; ni < 4; ni++) {
        int i = i0 + mtile * 16 + gr;
        int j = j0 + ntile * 32 + ni * 8 + 2 * tig;
        float2* p0 = reinterpret_cast<float2*>(&g_logits[((size_t)h * N_TOK + i) * N_TOK + j]);
        float2 v0 = *p0;
        v0.x += acc[ni][0]; v0.y += acc[ni][1];
        *p0 = v0;
        float2* p1 = reinterpret_cast<float2*>(&g_logits[((size_t)h * N_TOK + i + 8) * N_TOK + j]);
        float2 v1 = *p1;
        v1.x += acc[ni][2]; v1.y += acc[ni][3];
        *p1 = v1;
    }
}

// ---------------- K3b: row softmax ----------------
__global__ void softmax_kernel() {
    __shared__ float red[8];
    int i = blockIdx.x, h = blockIdx.y;
    float* row = &g_logits[((size_t)h * N_TOK + i) * N_TOK];
    int tid = threadIdx.x;
    float v0 = row[tid], v1 = row[tid + 256], v2 = row[tid + 512];
    float mx = fmaxf(v0, fmaxf(v1, v2));
    for (int o = 16; o; o >>= 1) mx = fmaxf(mx, __shfl_xor_sync(0xffffffffu, mx, o));
    if ((tid & 31) == 0) red[tid >> 5] = mx;
    __syncthreads();
    float m = red[0];
#pragma unroll
    for (int t = 1; t < 8; t++) m = fmaxf(m, red[t]);
    v0 = __expf(v0 - m); v1 = __expf(v1 - m); v2 = __expf(v2 - m);
    float sm = v0 + v1 + v2;
    for (int o = 16; o; o >>= 1) sm += __shfl_xor_sync(0xffffffffu, sm, o);
    __syncthreads();
    if ((tid & 31) == 0) red[tid >> 5] = sm;
    __syncthreads();
    float s = red[0];
#pragma unroll
    for (int t = 1; t < 8; t++) s += red[t];
    float inv = 1.0f / s;
    row[tid] = v0 * inv; row[tid + 256] = v1 * inv; row[tid + 512] = v2 * inv;
}

// ---------------- K3c: O = P @ V (tf32 MMA) ----------------
// block 256 thr; tile i=64, d=32 (full), K=768 in 64-j chunks.
// warp: mtile=w&3 (16 i), ntile=(w>>2)&1 (16 d); warps 0-3 / 4-7 duplicate m... no:
// 8 warps: mtile=w&3, ntile=w>>2 (0..1, 16 d each).
__global__ void attnv_kernel() {
    __shared__ float ps[64][68];
    __shared__ float vs[32][68];
    int h = blockIdx.y;
    int i0 = blockIdx.x * 64;
    int tid = threadIdx.x;
    int wid = tid >> 5, lane = tid & 31;
    int mtile = wid & 3, ntile = wid >> 2;
    int gr = lane >> 2, tig = lane & 3;
    float acc[2][4] = {};

    for (int j0 = 0; j0 < N_TOK; j0 += 64) {
#pragma unroll
        for (int it = 0; it < 4; it++) {
            int e = tid + it * 256;
            int r = e >> 4, c4 = (e & 15) * 4;
            float4 v = *reinterpret_cast<const float4*>(
                &g_logits[((size_t)h * N_TOK + i0 + r) * N_TOK + j0 + c4]);
            *reinterpret_cast<float4*>(&ps[r][c4]) = v;
        }
#pragma unroll
        for (int it = 0; it < 8; it++) {
            int e = tid + it * 256;
            int r = e >> 5, d = e & 31;
            vs[d][r] = g_v[(j0 + r) * D_MODEL + h * DH + d];
        }
        __syncthreads();
#pragma unroll
        for (int kk = 0; kk < 64; kk += 8) {
            int mr = mtile * 16 + gr;
            unsigned a0 = f2tf32(ps[mr][kk + tig]);
            unsigned a1 = f2tf32(ps[mr + 8][kk + tig]);
            unsigned a2 = f2tf32(ps[mr][kk + tig + 4]);
            unsigned a3 = f2tf32(ps[mr + 8][kk + tig + 4]);
#pragma unroll
            for (int ni = 0; ni < 2; ni++) {
                int nr = ntile * 16 + ni * 8 + gr;
                unsigned b0 = f2tf32(vs[nr][kk + tig]);
                unsigned b1 = f2tf32(vs[nr][kk + tig + 4]);
                mma_tf32(acc[ni], a0, a1, a2, a3, b0, b1);
            }
        }
        __syncthreads();
    }
#pragma unroll
    for (int ni = 0; ni < 2; ni++) {
        int m = i0 + mtile * 16 + gr;
        int d = ntile * 16 + ni * 8 + 2 * tig;
        *reinterpret_cast<float2*>(&g_o[m * D_MODEL + h * DH + d]) =
            make_float2(acc[ni][0], acc[ni][1]);
        *reinterpret_cast<float2*>(&g_o[(m + 8) * D_MODEL + h * DH + d]) =
            make_float2(acc[ni][2], acc[ni][3]);
    }
}

// ---------------- K4: out = (o * sigmoid(g)) @ Wo^T (tf32 MMA) ----------------
__global__ void out_kernel(const float* __restrict__ Wo, float* __restrict__ out) {
    __shared__ float ss[128][20];
    __shared__ float ws[64][20];
    int bm = blockIdx.y * 128, bn = blockIdx.x * 64;
    int tid = threadIdx.x;
    int wid = tid >> 5, lane = tid & 31;
    int mtile = wid & 3, ntile = wid >> 2;
    int gr = lane >> 2, tig = lane & 3;
    float acc[2][4][4] = {};

    for (int k0 = 0; k0 < D_MODEL; k0 += 16) {
#pragma unroll
        for (int it = 0; it < 2; it++) {
            int e = tid + it * 256;
            int r = e >> 2, c4 = (e & 3) * 4;
            float4 va = *reinterpret_cast<const float4*>(&g_o[(bm + r) * D_MODEL + k0 + c4]);
            float4 vg = *reinterpret_cast<const float4*>(&g_g[(bm + r) * D_MODEL + k0 + c4]);
            va.x *= 1.0f / (1.0f + __expf(-vg.x));
            va.y *= 1.0f / (1.0f + __expf(-vg.y));
            va.z *= 1.0f / (1.0f + __expf(-vg.z));
            va.w *= 1.0f / (1.0f + __expf(-vg.w));
            *reinterpret_cast<float4*>(&ss[r][c4]) = va;
        }
        {
            int r = tid >> 2, c4 = (tid & 3) * 4;
            float4 v = *reinterpret_cast<const float4*>(&Wo[(bn + r) * D_MODEL + k0 + c4]);
            *reinterpret_cast<float4*>(&ws[r][c4]) = v;
        }
        __syncthreads();
#pragma unroll
        for (int kk = 0; kk < 16; kk += 8) {
            unsigned a[2][4];
#pragma unroll
            for (int mi = 0; mi < 2; mi++) {
                int mr = mtile * 32 + mi * 16 + gr;
                a[mi][0] = f2tf32(ss[mr][kk + tig]);
                a[mi][1] = f2tf32(ss[mr + 8][kk + tig]);
                a[mi][2] = f2tf32(ss[mr][kk + tig + 4]);
                a[mi][3] = f2tf32(ss[mr + 8][kk + tig + 4]);
            }
#pragma unroll
            for (int ni = 0; ni < 4; ni++) {
                int nr = ntile * 32 + ni * 8 + gr;
                unsigned b0 = f2tf32(ws[nr][kk + tig]);
                unsigned b1 = f2tf32(ws[nr][kk + tig + 4]);
#pragma unroll
                for (int mi = 0; mi < 2; mi++)
                    mma_tf32(acc[mi][ni], a[mi][0], a[mi][1], a[mi][2], a[mi][3], b0, b1);
            }
        }
        __syncthreads();
    }
#pragma unroll
    for (int mi = 0; mi < 2; mi++) {
#pragma unroll
        for (int ni = 0; ni < 4; ni++) {
            int m = bm + mtile * 32 + mi * 16 + gr;
            int n = bn + ntile * 32 + ni * 8 + 2 * tig;
            *reinterpret_cast<float2*>(&out[m * D_MODEL + n]) =
                make_float2(acc[mi][ni][0], acc[mi][ni][1]);
            *reinterpret_cast<float2*>(&out[(m + 8) * D_MODEL + n]) =
                make_float2(acc[mi][ni][2], acc[mi][ni][3]);
        }
    }
}

// ---------------- launch ----------------
extern "C" void kernel_launch(void* const* d_in, const int* in_sizes, int n_in,
                              void* d_out, int out_size) {
    const float* s   = (const float*)d_in[0];
    const float* z   = (const float*)d_in[1];
    const float* Wq  = (const float*)d_in[2];
    const float* bq  = (const float*)d_in[3];
    const float* Wk  = (const float*)d_in[4];
    const float* Wv  = (const float*)d_in[5];
    const float* Wg  = (const float*)d_in[6];
    const float* Wo  = (const float*)d_in[7];
    const float* lnw = (const float*)d_in[8];
    const float* lnb = (const float*)d_in[9];
    const float* Wz  = (const float*)d_in[10];
    float* out = (float*)d_out;

    prep_kernel<<<1, 128>>>(Wz, lnw, lnb);
    proj_kernel<<<dim3(D_MODEL / 64, N_TOK / 128, 4), 256>>>(s, Wq, bq, Wk, Wv, Wg);
    bias_kernel<<<dim3(N_TOK / 64, N_TOK), 256>>>(z);
    logits_kernel<<<dim3(N_TOK / 64, N_TOK / 64, NH), 256>>>();
    softmax_kernel<<<dim3(N_TOK, NH), 256>>>();
    attnv_kernel<<<dim3(N_TOK / 64, NH), 256>>>();
    out_kernel<<<dim3(D_MODEL / 64, N_TOK / 128), 256>>>(Wo, out);
}